// round 6
// baseline (speedup 1.0000x reference)
#include <cuda_runtime.h>
#include <math.h>

#define NN 512
#define SS 64
#define CC 1024
#define BB 10
#define SB 4                        // s-positions per CTA
#define CHUNKS (SS / SB)            // 16 CTAs per row
#define PI_ELEMS (NN * SS * CC)

// ---------------------------------------------------------------------------
// Single fused kernel. 8192 CTAs x 256 threads (~8 CTAs/SM).
// Per CTA: row hist (64 smem atomics) -> Z via <=64 nonzero bins
// (Z = 1024 + sum_distinct (e^h - 1)) -> SB lse values -> mask-folded
// streaming stores. No global scratch at all.
// ---------------------------------------------------------------------------
__global__ __launch_bounds__(256) void spop_kernel(
    const int* __restrict__ ban_ids,
    const int* __restrict__ item_ids,
    float* __restrict__ out)
{
    __shared__ int      s_hist[CC];
    __shared__ int      s_ids[SS];
    __shared__ int      s_ban[SB * BB];
    __shared__ unsigned s_mask[SB][CC / 32];
    __shared__ float    s_l[SB];
    __shared__ int      s_last;
    __shared__ float    s_Z;

    const int blk  = blockIdx.x;
    const int n    = blk >> 4;               // CHUNKS == 16
    const int s0   = (blk & 15) * SB;
    const int tid  = threadIdx.x;
    const int lane = tid & 31;

    // ---- init + loads, all independent ----
    reinterpret_cast<int4*>(s_hist)[tid] = make_int4(0, 0, 0, 0);
    if (tid < SS) s_ids[tid] = item_ids[n * SS + tid];
    int myban = 0;
    if (tid < SB * BB) {
        myban = ban_ids[(n * SS + s0) * BB + tid];
        s_ban[tid] = myban;
    }
    if (tid >= 64 && tid < 64 + SB * (CC / 32))
        (&s_mask[0][0])[tid - 64] = 0u;
    if (tid == 0) { s_last = -1; s_Z = 1024.0f; }
    // v tail zeros (chunk 0 of each row)
    if ((blk & 15) == 0 && tid < SS) out[PI_ELEMS + n * SS + tid] = 0.0f;
    __syncthreads();

    // ---- last non-pad (PAD == 0) + ban bitmask build ----
    if (tid < SS && s_ids[tid] != 0) atomicMax(&s_last, tid);
    if (tid < SB * BB)
        atomicOr(&s_mask[tid / BB][myban >> 5], 1u << (myban & 31));
    __syncthreads();

    // ---- histogram, dropping the last non-pad element ----
    const bool counted = (tid < SS) && (s_ids[tid] != 0) && (tid != s_last);
    if (counted) atomicAdd(&s_hist[s_ids[tid]], 1);
    __syncthreads();

    // ---- Z = 1024 + sum over DISTINCT counted ids of (e^h - 1) ----
    {
        float zp = 0.0f;
        if (counted) {
            const int id = s_ids[tid];
            bool first = true;
            #pragma unroll
            for (int j = 0; j < SS; ++j) {
                if (j < tid) {
                    const bool cj = (s_ids[j] != 0) && (j != s_last);
                    if (cj && s_ids[j] == id) first = false;
                }
            }
            if (first) zp = expf((float)s_hist[id]) - 1.0f;
        }
        #pragma unroll
        for (int off = 16; off; off >>= 1)
            zp += __shfl_xor_sync(0xffffffffu, zp, off);
        if (tid < SS && lane == 0 && zp != 0.0f) atomicAdd(&s_Z, zp);
    }
    __syncthreads();

    // ---- per-s lse with rank-10 distinct-banned correction ----
    if (tid < SB) {
        float corr = 0.0f;
        int ids[BB];
        #pragma unroll
        for (int j = 0; j < BB; ++j) {
            const int id = s_ban[tid * BB + j];
            ids[j] = id;
            bool dup = false;
            #pragma unroll
            for (int k = 0; k < BB; ++k) if (k < j) dup |= (ids[k] == id);
            if (!dup) corr += expf((float)s_hist[id]);
        }
        s_l[tid] = logf(fmaxf(s_Z - corr, 1e-35f));
    }
    __syncthreads();

    // ---- streaming stores: counts from smem, mask folded, __stcs hint ----
    const int c0 = tid * 4;
    const int4 h = reinterpret_cast<const int4*>(s_hist)[tid];
    const float f0 = (float)h.x, f1 = (float)h.y;
    const float f2 = (float)h.z, f3 = (float)h.w;

    float4* __restrict__ out4 =
        reinterpret_cast<float4*>(out) + (n * SS + s0) * (CC / 4) + tid;
    #pragma unroll
    for (int s = 0; s < SB; ++s) {
        const float    l = s_l[s];
        const unsigned m = s_mask[s][c0 >> 5] >> (c0 & 31);
        float4 o;
        o.x = f0 - l - ((m & 1u) ? 1e9f : 0.0f);
        o.y = f1 - l - ((m & 2u) ? 1e9f : 0.0f);
        o.z = f2 - l - ((m & 4u) ? 1e9f : 0.0f);
        o.w = f3 - l - ((m & 8u) ? 1e9f : 0.0f);
        __stcs(&out4[s * (CC / 4)], o);       // streaming store: evict-first
    }
}

extern "C" void kernel_launch(void* const* d_in, const int* in_sizes, int n_in,
                              void* d_out, int out_size) {
    // metadata order: null_w (f32, unused), ban_ids (i32 [N,S,B]), item_ids (i32 [N,S])
    const int* ban_ids  = (const int*)d_in[1];
    const int* item_ids = (const int*)d_in[2];
    float* out = (float*)d_out;

    spop_kernel<<<NN * CHUNKS, 256>>>(ban_ids, item_ids, out);
}

// round 7
// speedup vs baseline: 1.7651x; 1.7651x over previous
#include <cuda_runtime.h>
#include <math.h>

#define NN 512
#define SS 64
#define CC 1024
#define BB 10
#define SB 4                        // s-positions per streaming CTA
#define PI_ELEMS (NN * SS * CC)

__device__ unsigned char g_counts[NN * CC];   // row histograms, u8 (<=63)
__device__ float         g_lse[NN * SS];      // per-(n,s) log-partition

// ---------------------------------------------------------------------------
// Kernel A (primary): per-row hist + Z + all 64 lse + v zeros.
// 512 CTAs x 256 threads. ~2.6us.
// ---------------------------------------------------------------------------
__global__ __launch_bounds__(256) void row_stats_kernel(
    const int* __restrict__ ban_ids,
    const int* __restrict__ item_ids,
    float* __restrict__ out)
{
    __shared__ int   s_hist[CC];
    __shared__ int   s_ids[SS];
    __shared__ int   s_ban[SS * BB];
    __shared__ int   s_last;
    __shared__ float s_red[8];
    __shared__ float s_Z;

    const int n    = blockIdx.x;
    const int tid  = threadIdx.x;
    const int lane = tid & 31;
    const int wrp  = tid >> 5;

    #pragma unroll
    for (int i = tid; i < CC; i += 256) s_hist[i] = 0;
    if (tid < SS) s_ids[tid] = item_ids[n * SS + tid];
    #pragma unroll
    for (int i = tid; i < SS * BB; i += 256) s_ban[i] = ban_ids[n * SS * BB + i];
    if (tid == 0) s_last = -1;
    if (tid < SS) out[PI_ELEMS + n * SS + tid] = 0.0f;     // v tail zeros
    __syncthreads();

    if (tid < SS && s_ids[tid] != 0) atomicMax(&s_last, tid);   // PAD == 0
    __syncthreads();

    if (tid < SS && s_ids[tid] != 0 && tid != s_last)
        atomicAdd(&s_hist[s_ids[tid]], 1);
    __syncthreads();

    // pack 4 u8 counts + partial Z  (counts<=63: exp never overflows)
    const int c0 = tid * 4;
    const int h0 = s_hist[c0 + 0], h1 = s_hist[c0 + 1];
    const int h2 = s_hist[c0 + 2], h3 = s_hist[c0 + 3];
    reinterpret_cast<unsigned*>(g_counts)[n * (CC / 4) + tid] =
        (unsigned)h0 | ((unsigned)h1 << 8) | ((unsigned)h2 << 16) | ((unsigned)h3 << 24);

    float z = expf((float)h0) + expf((float)h1) + expf((float)h2) + expf((float)h3);
    #pragma unroll
    for (int off = 16; off; off >>= 1)
        z += __shfl_xor_sync(0xffffffffu, z, off);
    if (lane == 0) s_red[wrp] = z;
    __syncthreads();
    if (tid == 0) {
        float t = 0.0f;
        #pragma unroll
        for (int w = 0; w < 8; ++w) t += s_red[w];
        s_Z = t;
    }
    __syncthreads();

    // per-s log-partition with rank-10 distinct-banned correction
    if (tid < SS) {
        const float Z = s_Z;
        float corr = 0.0f;
        int ids[BB];
        #pragma unroll
        for (int j = 0; j < BB; ++j) {
            const int id = s_ban[tid * BB + j];
            ids[j] = id;
            bool dup = false;
            #pragma unroll
            for (int k = 0; k < BB; ++k) if (k < j) dup |= (ids[k] == id);
            if (!dup) corr += expf((float)s_hist[id]);
        }
        g_lse[n * SS + tid] = logf(fmaxf(Z - corr, 1e-35f));
    }
}

// ---------------------------------------------------------------------------
// Kernel B (secondary, PDL): streamer identical to R4's best (24.2us):
// 8192 CTAs x 256 threads, SB=4, mask folded into single store pass.
// All A-independent work (ban load, mask build) happens BEFORE the grid
// dependency sync, so it overlaps kernel A's execution.
// ---------------------------------------------------------------------------
__global__ __launch_bounds__(256) void stream_kernel(
    const int* __restrict__ ban_ids,
    float* __restrict__ out)
{
    __shared__ unsigned s_mask[SB][CC / 32];
    __shared__ float    s_l[SB];

    const int blk = blockIdx.x;
    const int n   = blk >> 4;                 // SS/SB == 16 chunks per row
    const int s0  = (blk & 15) * SB;
    const int tid = threadIdx.x;
    const int c0  = tid * 4;

    // ---- A-independent prologue (overlaps row_stats under PDL) ----
    if (tid < SB * (CC / 32))
        (&s_mask[0][0])[tid] = 0u;
    int myban = 0;
    if (tid < SB * BB) myban = ban_ids[(n * SS + s0) * BB + tid];
    __syncthreads();
    if (tid < SB * BB)
        atomicOr(&s_mask[tid / BB][myban >> 5], 1u << (myban & 31));

    // ---- wait for kernel A's g_counts / g_lse ----
    cudaGridDependencySynchronize();

    const unsigned cw =
        __ldg(&reinterpret_cast<const unsigned*>(g_counts)[n * (CC / 4) + tid]);
    if (tid < SB) s_l[tid] = g_lse[n * SS + s0 + tid];
    __syncthreads();

    const float f0 = (float)( cw        & 0xffu);
    const float f1 = (float)((cw >>  8) & 0xffu);
    const float f2 = (float)((cw >> 16) & 0xffu);
    const float f3 = (float)( cw >> 24         );

    float4* __restrict__ out4 = reinterpret_cast<float4*>(out);
    const int base = (n * SS + s0) * (CC / 4);
    #pragma unroll
    for (int s = 0; s < SB; ++s) {
        const float    l = s_l[s];
        const unsigned m = s_mask[s][c0 >> 5] >> (c0 & 31);
        float4 o;
        o.x = f0 - l - ((m & 1u) ? 1e9f : 0.0f);
        o.y = f1 - l - ((m & 2u) ? 1e9f : 0.0f);
        o.z = f2 - l - ((m & 4u) ? 1e9f : 0.0f);
        o.w = f3 - l - ((m & 8u) ? 1e9f : 0.0f);
        out4[base + s * (CC / 4) + tid] = o;
    }
}

extern "C" void kernel_launch(void* const* d_in, const int* in_sizes, int n_in,
                              void* d_out, int out_size) {
    // metadata order: null_w (f32, unused), ban_ids (i32 [N,S,B]), item_ids (i32 [N,S])
    const int* ban_ids  = (const int*)d_in[1];
    const int* item_ids = (const int*)d_in[2];
    float* out = (float*)d_out;

    row_stats_kernel<<<NN, 256>>>(ban_ids, item_ids, out);

    // Streamer with Programmatic Dependent Launch: overlap its launch +
    // prologue with row_stats; cudaGridDependencySynchronize() gates the
    // g_counts/g_lse reads.
    cudaLaunchAttribute attr[1];
    attr[0].id = cudaLaunchAttributeProgrammaticStreamSerialization;
    attr[0].val.programmaticStreamSerializationAllowed = 1;

    cudaLaunchConfig_t cfg = {};
    cfg.gridDim  = dim3(NN * (SS / SB), 1, 1);
    cfg.blockDim = dim3(256, 1, 1);
    cfg.dynamicSmemBytes = 0;
    cfg.stream   = 0;
    cfg.attrs    = attr;
    cfg.numAttrs = 1;

    cudaLaunchKernelEx(&cfg, stream_kernel, ban_ids, (float*)out);
}